// round 2
// baseline (speedup 1.0000x reference)
#include <cuda_runtime.h>
#include <cstdint>

// ============================================================================
// InfoNCE (gradcache) loss: N=16384, D=128, temperature 0.07
// loss = mean_i( log(sim_v_i) - s_ii * inv_t )
//   sim_v_i = sum_j exp(q_i.d_j/t) + sum_j exp(q_i.q_j/t) - exp(inv_t)
// Strategy: normalize+tf32-round -> tiled mma.sync tf32 GEMM fused with
// exp(row-sum) -> deterministic reduction.
// ============================================================================

#define N_ROWS 16384
#define D_DIM  128
#define SPLITS 16          // column-space splits of the 2N=32768 columns
#define STRIPE ((2 * N_ROWS) / SPLITS)   // 2048 columns per split
#define BM 128             // q-rows per block
#define BN 64              // columns per shared-memory chunk
#define PITCH 132          // padded floats per row in smem (conflict-free)
#define CHUNKS (STRIPE / BN)             // 32
#define SMEM_BYTES (((BM + BN) * PITCH) * 4)   // 101376 B

#define INV_T      14.285714285714286f        // 1/0.07 (fp32 of the double)
#define SCALE_L2E  20.609929155556618f        // inv_t * log2(e)

static __device__ float g_Qn[N_ROWS * D_DIM];
static __device__ float g_Dn[N_ROWS * D_DIM];
static __device__ float g_diag[N_ROWS];
static __device__ float g_partial[SPLITS * N_ROWS];

// ---------------------------------------------------------------------------

__device__ __forceinline__ float tf32_round(float x) {
    uint32_t u;
    asm("cvt.rna.tf32.f32 %0, %1;" : "=r"(u) : "f"(x));
    return __uint_as_float(u);
}

__device__ __forceinline__ float ex2f(float x) {
    float y;
    asm("ex2.approx.ftz.f32 %0, %1;" : "=f"(y) : "f"(x));
    return y;
}

__device__ __forceinline__ void mma_tf32(float (&c)[4], const uint32_t (&a)[4],
                                         uint32_t b0, uint32_t b1) {
    asm volatile(
        "mma.sync.aligned.m16n8k8.row.col.f32.tf32.tf32.f32 "
        "{%0,%1,%2,%3}, {%4,%5,%6,%7}, {%8,%9}, {%0,%1,%2,%3};\n"
        : "+f"(c[0]), "+f"(c[1]), "+f"(c[2]), "+f"(c[3])
        : "r"(a[0]), "r"(a[1]), "r"(a[2]), "r"(a[3]), "r"(b0), "r"(b1));
}

// ---------------------------------------------------------------------------
// Kernel 1: L2-normalize rows of q and d, round to tf32, store to scratch.
// One warp per row; rows [0,N) = q, [N,2N) = d.
__global__ void knorm(const float* __restrict__ q, const float* __restrict__ d) {
    int wg   = (blockIdx.x * blockDim.x + threadIdx.x) >> 5;
    int lane = threadIdx.x & 31;
    if (wg >= 2 * N_ROWS) return;

    const float* src;
    float* dst;
    int row;
    if (wg < N_ROWS) { row = wg;          src = q; dst = g_Qn; }
    else             { row = wg - N_ROWS; src = d; dst = g_Dn; }

    float4 v = reinterpret_cast<const float4*>(src + (size_t)row * D_DIM)[lane];
    float ss = v.x * v.x + v.y * v.y + v.z * v.z + v.w * v.w;
    #pragma unroll
    for (int o = 16; o > 0; o >>= 1) ss += __shfl_xor_sync(0xFFFFFFFFu, ss, o);
    float inv = 1.0f / sqrtf(ss);
    v.x = tf32_round(v.x * inv);
    v.y = tf32_round(v.y * inv);
    v.z = tf32_round(v.z * inv);
    v.w = tf32_round(v.w * inv);
    reinterpret_cast<float4*>(dst + (size_t)row * D_DIM)[lane] = v;
}

// ---------------------------------------------------------------------------
// Kernel 2: diagonal dots s_ii = <qn_i, dn_i>. One warp per row.
__global__ void kdiag() {
    int wg   = (blockIdx.x * blockDim.x + threadIdx.x) >> 5;
    int lane = threadIdx.x & 31;
    if (wg >= N_ROWS) return;
    float4 a = reinterpret_cast<const float4*>(g_Qn + (size_t)wg * D_DIM)[lane];
    float4 b = reinterpret_cast<const float4*>(g_Dn + (size_t)wg * D_DIM)[lane];
    float s = a.x * b.x + a.y * b.y + a.z * b.z + a.w * b.w;
    #pragma unroll
    for (int o = 16; o > 0; o >>= 1) s += __shfl_xor_sync(0xFFFFFFFFu, s, o);
    if (lane == 0) g_diag[wg] = s;
}

// ---------------------------------------------------------------------------
// Kernel 3: main fused GEMM + exp + row-sum.
// Grid: (N/BM, SPLITS). Block 256 threads = 8 warps arranged 4(m) x 2(n).
// Each block: rows [by*128, +128) vs column stripe [bz*2048, +2048) of the
// concatenated column matrix [Dn ; Qn]. Writes g_partial[bz][row].
__global__ void __launch_bounds__(256, 2) kmain() {
    extern __shared__ float smem[];
    float* sQ = smem;                 // [BM][PITCH]
    float* sC = smem + BM * PITCH;    // [BN][PITCH]

    const int tid  = threadIdx.x;
    const int lane = tid & 31;
    const int warp = tid >> 5;
    const int wm = warp >> 1;         // 0..3  (32-row band)
    const int wn = warp & 1;          // 0..1  (32-col band)
    const int g = lane >> 2;          // 0..7
    const int t = lane & 3;           // 0..3
    const int by = blockIdx.x;
    const int bz = blockIdx.y;

    // ---- load Q tile (128 rows x 128 k) into padded smem ----
    {
        const float4* qbase =
            reinterpret_cast<const float4*>(g_Qn + (size_t)by * BM * D_DIM);
        #pragma unroll
        for (int i = tid; i < BM * (D_DIM / 4); i += 256) {
            int r = i >> 5, c4 = i & 31;
            float4 v = qbase[i];
            *reinterpret_cast<float4*>(sQ + r * PITCH + c4 * 4) = v;
        }
    }

    float rs[4] = {0.f, 0.f, 0.f, 0.f};   // per-thread partial row sums

    const int col0 = bz * STRIPE;
    const uint32_t* sQu = reinterpret_cast<const uint32_t*>(sQ);
    const uint32_t* sCu = reinterpret_cast<const uint32_t*>(sC);
    const int aBase = (wm * 32 + g) * PITCH + t;
    const int bBase = (wn * 32 + g) * PITCH + t;

    for (int ch = 0; ch < CHUNKS; ch++) {
        const int gc = col0 + ch * BN;   // aligned to 64; never straddles D/Q
        const float4* cbase = (gc < N_ROWS)
            ? reinterpret_cast<const float4*>(g_Dn + (size_t)gc * D_DIM)
            : reinterpret_cast<const float4*>(g_Qn + (size_t)(gc - N_ROWS) * D_DIM);

        __syncthreads();   // previous chunk's compute done before overwrite
        #pragma unroll
        for (int i = tid; i < BN * (D_DIM / 4); i += 256) {
            int r = i >> 5, c4 = i & 31;
            float4 v = cbase[i];
            *reinterpret_cast<float4*>(sC + r * PITCH + c4 * 4) = v;
        }
        __syncthreads();

        float acc[2][4][4];
        #pragma unroll
        for (int mt = 0; mt < 2; mt++)
            #pragma unroll
            for (int nt = 0; nt < 4; nt++)
                #pragma unroll
                for (int c = 0; c < 4; c++) acc[mt][nt][c] = 0.f;

        #pragma unroll
        for (int ks = 0; ks < D_DIM / 8; ks++) {
            const int ko = ks * 8;
            uint32_t a[2][4];
            #pragma unroll
            for (int mt = 0; mt < 2; mt++) {
                int o = aBase + mt * 16 * PITCH + ko;
                a[mt][0] = sQu[o];
                a[mt][1] = sQu[o + 8 * PITCH];
                a[mt][2] = sQu[o + 4];
                a[mt][3] = sQu[o + 8 * PITCH + 4];
            }
            #pragma unroll
            for (int nt = 0; nt < 4; nt++) {
                int ob = bBase + nt * 8 * PITCH + ko;
                uint32_t b0 = sCu[ob];
                uint32_t b1 = sCu[ob + 4];
                mma_tf32(acc[0][nt], a[0], b0, b1);
                mma_tf32(acc[1][nt], a[1], b0, b1);
            }
        }

        // fused exp + row-sum accumulation (EX2 pipe, overlaps next iters)
        #pragma unroll
        for (int mt = 0; mt < 2; mt++)
            #pragma unroll
            for (int nt = 0; nt < 4; nt++) {
                rs[mt * 2 + 0] += ex2f(acc[mt][nt][0] * SCALE_L2E)
                                + ex2f(acc[mt][nt][1] * SCALE_L2E);
                rs[mt * 2 + 1] += ex2f(acc[mt][nt][2] * SCALE_L2E)
                                + ex2f(acc[mt][nt][3] * SCALE_L2E);
            }
    }

    // ---- reduce: quad (over t lanes) -> shared (over wn warps) -> global ----
    #pragma unroll
    for (int r = 0; r < 4; r++) {
        rs[r] += __shfl_xor_sync(0xFFFFFFFFu, rs[r], 1);
        rs[r] += __shfl_xor_sync(0xFFFFFFFFu, rs[r], 2);
    }
    __syncthreads();
    float* srow = smem;   // reuse: [2][BM]
    if (t == 0) {
        #pragma unroll
        for (int r = 0; r < 4; r++) {
            int row_local = wm * 32 + (r >> 1) * 16 + (r & 1) * 8 + g;
            srow[wn * BM + row_local] = rs[r];
        }
    }
    __syncthreads();
    if (tid < BM) {
        g_partial[(size_t)bz * N_ROWS + by * BM + tid] =
            srow[tid] + srow[BM + tid];
    }
}

// ---------------------------------------------------------------------------
// Kernel 4: deterministic final reduction (double accumulators).
__global__ void kreduce(float* __restrict__ out) {
    __shared__ double red[256];
    const int tid = threadIdx.x;
    const float exp_self = expf(INV_T);
    double local = 0.0;
    for (int i = tid; i < N_ROWS; i += 256) {
        float sv = 0.f;
        #pragma unroll
        for (int s = 0; s < SPLITS; s++) sv += g_partial[s * N_ROWS + i];
        sv -= exp_self;
        local += (double)(logf(sv) - g_diag[i] * INV_T);
    }
    red[tid] = local;
    __syncthreads();
    #pragma unroll
    for (int o = 128; o > 0; o >>= 1) {
        if (tid < o) red[tid] += red[tid + o];
        __syncthreads();
    }
    if (tid == 0) out[0] = (float)(red[0] / (double)N_ROWS);
}

// ---------------------------------------------------------------------------
extern "C" void kernel_launch(void* const* d_in, const int* in_sizes, int n_in,
                              void* d_out, int out_size) {
    const float* q = (const float*)d_in[0];
    const float* d = (const float*)d_in[1];

    cudaFuncSetAttribute(kmain, cudaFuncAttributeMaxDynamicSharedMemorySize,
                         SMEM_BYTES);

    knorm<<<(2 * N_ROWS) / 8, 256>>>(q, d);
    kdiag<<<N_ROWS / 8, 256>>>();
    kmain<<<dim3(N_ROWS / BM, SPLITS), 256, SMEM_BYTES>>>();
    kreduce<<<1, 256>>>((float*)d_out);
}

// round 4
// speedup vs baseline: 2.1013x; 2.1013x over previous
#include <cuda_runtime.h>
#include <cuda_fp16.h>
#include <cstdint>

// ============================================================================
// InfoNCE (gradcache): N=16384, D=128, t=0.07
// f16 mma.sync.m16n8k16 tiled GEMM fused with exp/row-sum.
// (tcgen05 is unavailable: harness compiles for plain sm_100 target.)
// q.q self-term is skipped EXACTLY in the epilogue (no exp(1/t) cancellation).
// ============================================================================

#define N_ROWS 16384
#define D_DIM  128
#define SPLITS 16
#define STRIPE ((2 * N_ROWS) / SPLITS)   // 2048 columns per split
#define BM 128
#define BN 128
#define CHUNKS (STRIPE / BN)             // 16

#define PITCH_U 68                        // u32 units per row (272 B), conflict-free
#define ROW_B  (PITCH_U * 4)
#define SM_Q   0
#define SM_C0  (BM * ROW_B)              // 34816
#define SM_C1  (SM_C0 + BN * ROW_B)      // 69632
#define SMEM_BYTES (SM_C1 + BN * ROW_B)  // 104448

#define INV_T     14.285714285714286f
#define SCALE_L2E 20.609929155556618f    // (1/0.07) * log2(e)

static __device__ __half g_Qh[N_ROWS * D_DIM];
static __device__ __half g_Dh[N_ROWS * D_DIM];
static __device__ float  g_diag[N_ROWS];
static __device__ float  g_partial[SPLITS * N_ROWS];
static __device__ double g_red[64];

// ---------------------------------------------------------------------------
__device__ __forceinline__ uint32_t smem_u32(const void* p) {
    uint32_t a;
    asm("{ .reg .u64 t; cvta.to.shared.u64 t, %1; cvt.u32.u64 %0, t; }"
        : "=r"(a) : "l"(p));
    return a;
}
__device__ __forceinline__ float ex2f(float x) {
    float y; asm("ex2.approx.ftz.f32 %0, %1;" : "=f"(y) : "f"(x)); return y;
}
__device__ __forceinline__ void cp16(uint32_t dst, const void* src) {
    asm volatile("cp.async.cg.shared.global [%0], [%1], 16;"
                 :: "r"(dst), "l"(src) : "memory");
}
#define CP_COMMIT() asm volatile("cp.async.commit_group;" ::: "memory")
#define CP_WAIT0()  asm volatile("cp.async.wait_group 0;" ::: "memory")
#define CP_WAIT1()  asm volatile("cp.async.wait_group 1;" ::: "memory")

__device__ __forceinline__ void mma_f16(float (&c)[4], const uint32_t (&a)[4],
                                        uint32_t b0, uint32_t b1) {
    asm volatile(
        "mma.sync.aligned.m16n8k16.row.col.f32.f16.f16.f32 "
        "{%0,%1,%2,%3}, {%4,%5,%6,%7}, {%8,%9}, {%0,%1,%2,%3};\n"
        : "+f"(c[0]), "+f"(c[1]), "+f"(c[2]), "+f"(c[3])
        : "r"(a[0]), "r"(a[1]), "r"(a[2]), "r"(a[3]), "r"(b0), "r"(b1));
}

// ---------------------------------------------------------------------------
// Kernel 1: L2-normalize rows -> f16. One warp per row.
__global__ void knorm(const float* __restrict__ q, const float* __restrict__ d) {
    int wg = (blockIdx.x * blockDim.x + threadIdx.x) >> 5;
    int lane = threadIdx.x & 31;
    if (wg >= 2 * N_ROWS) return;
    const float* src;
    __half* dst;
    int row;
    if (wg < N_ROWS) { row = wg;          src = q; dst = g_Qh; }
    else             { row = wg - N_ROWS; src = d; dst = g_Dh; }

    float4 v = reinterpret_cast<const float4*>(src + (size_t)row * D_DIM)[lane];
    float ss = v.x * v.x + v.y * v.y + v.z * v.z + v.w * v.w;
    #pragma unroll
    for (int o = 16; o > 0; o >>= 1) ss += __shfl_xor_sync(0xFFFFFFFFu, ss, o);
    float inv = rsqrtf(ss);
    __half2* o2 = reinterpret_cast<__half2*>(dst + (size_t)row * D_DIM);
    o2[lane * 2 + 0] = __floats2half2_rn(v.x * inv, v.y * inv);
    o2[lane * 2 + 1] = __floats2half2_rn(v.z * inv, v.w * inv);
}

// Kernel 2: diagonal dots from the f16 values (consistent with the GEMM).
__global__ void kdiag() {
    int wg = (blockIdx.x * blockDim.x + threadIdx.x) >> 5;
    int lane = threadIdx.x & 31;
    if (wg >= N_ROWS) return;
    const __half2* qa = reinterpret_cast<const __half2*>(g_Qh + (size_t)wg * D_DIM);
    const __half2* da = reinterpret_cast<const __half2*>(g_Dh + (size_t)wg * D_DIM);
    float s = 0.f;
    #pragma unroll
    for (int k = 0; k < 2; k++) {
        float2 a = __half22float2(qa[lane * 2 + k]);
        float2 b = __half22float2(da[lane * 2 + k]);
        s += a.x * b.x + a.y * b.y;
    }
    #pragma unroll
    for (int o = 16; o > 0; o >>= 1) s += __shfl_xor_sync(0xFFFFFFFFu, s, o);
    if (lane == 0) g_diag[wg] = s;
}

// ---------------------------------------------------------------------------
// Kernel 3: main fused GEMM + exp + row-sum.
// Grid (N/BM, SPLITS). 256 threads = 8 warps as 4(m) x 2(n).
// Warp tile: 32 rows (mt=2) x 64 cols (nt=8). cp.async double-buffered B.
__global__ void __launch_bounds__(256, 2) kmain() {
    extern __shared__ char smem[];
    const uint32_t sb = smem_u32(smem);
    const int tid = threadIdx.x, lane = tid & 31, warp = tid >> 5;
    const int wm = warp >> 1, wn = warp & 1;
    const int g = lane >> 2, t = lane & 3;
    const int by = blockIdx.x, bz = blockIdx.y;
    const int col0 = bz * STRIPE;

    // issue A tile (8 x 16B per thread) + chunk 0, as one cp.async group
    {
        const uint4* ab = reinterpret_cast<const uint4*>(g_Qh + (size_t)by * BM * D_DIM);
        #pragma unroll
        for (int i = 0; i < 8; i++) {
            int u4 = tid + i * 256;                 // 0..2047
            uint32_t dst = sb + SM_Q + (u4 >> 4) * ROW_B + (u4 & 15) * 16;
            cp16(dst, ab + u4);
        }
        const uint4* cb = (col0 < N_ROWS)
            ? reinterpret_cast<const uint4*>(g_Dh + (size_t)col0 * D_DIM)
            : reinterpret_cast<const uint4*>(g_Qh + (size_t)(col0 - N_ROWS) * D_DIM);
        #pragma unroll
        for (int i = 0; i < 8; i++) {
            int u4 = tid + i * 256;
            uint32_t dst = sb + SM_C0 + (u4 >> 4) * ROW_B + (u4 & 15) * 16;
            cp16(dst, cb + u4);
        }
        CP_COMMIT();
    }

    float rs[4] = {0.f, 0.f, 0.f, 0.f};
    const uint32_t* sQu = reinterpret_cast<const uint32_t*>(smem);
    const int aRow = wm * 32 + g;

    for (int ch = 0; ch < CHUNKS; ch++) {
        const uint32_t coff = (ch & 1) ? SM_C1 : SM_C0;
        if (ch + 1 < CHUNKS) {
            const int gc = col0 + (ch + 1) * BN;
            const uint4* cb = (gc < N_ROWS)
                ? reinterpret_cast<const uint4*>(g_Dh + (size_t)gc * D_DIM)
                : reinterpret_cast<const uint4*>(g_Qh + (size_t)(gc - N_ROWS) * D_DIM);
            const uint32_t noff = (ch & 1) ? SM_C0 : SM_C1;
            #pragma unroll
            for (int i = 0; i < 8; i++) {
                int u4 = tid + i * 256;
                cp16(sb + noff + (u4 >> 4) * ROW_B + (u4 & 15) * 16, cb + u4);
            }
            CP_COMMIT();
            CP_WAIT1();
        } else {
            CP_WAIT0();
        }
        __syncthreads();

        const uint32_t* sCu = reinterpret_cast<const uint32_t*>(smem + coff);

        float acc[2][8][4];
        #pragma unroll
        for (int mt = 0; mt < 2; mt++)
            #pragma unroll
            for (int nt = 0; nt < 8; nt++)
                #pragma unroll
                for (int c = 0; c < 4; c++) acc[mt][nt][c] = 0.f;

        #pragma unroll
        for (int ks = 0; ks < 8; ks++) {
            const int kb = ks * 8;
            uint32_t a[2][4];
            #pragma unroll
            for (int mt = 0; mt < 2; mt++) {
                int r0 = (aRow + mt * 16) * PITCH_U + kb + t;
                a[mt][0] = sQu[r0];
                a[mt][1] = sQu[r0 + 8 * PITCH_U];
                a[mt][2] = sQu[r0 + 4];
                a[mt][3] = sQu[r0 + 8 * PITCH_U + 4];
            }
            #pragma unroll
            for (int nt = 0; nt < 8; nt++) {
                int cbi = (wn * 64 + nt * 8 + g) * PITCH_U + kb + t;
                uint32_t b0 = sCu[cbi];
                uint32_t b1 = sCu[cbi + 4];
                mma_f16(acc[0][nt], a[0], b0, b1);
                mma_f16(acc[1][nt], a[1], b0, b1);
            }
        }

        // epilogue: exp + row-sum. Skip q.q self term exactly in the one
        // diagonal chunk (BN==BM, both 128-aligned -> diag iff gc==N+by*128).
        const bool diag = (col0 + ch * BN) == (N_ROWS + by * BM);
        if (!diag) {
            #pragma unroll
            for (int mt = 0; mt < 2; mt++)
                #pragma unroll
                for (int nt = 0; nt < 8; nt++) {
                    rs[mt * 2 + 0] += ex2f(acc[mt][nt][0] * SCALE_L2E)
                                    + ex2f(acc[mt][nt][1] * SCALE_L2E);
                    rs[mt * 2 + 1] += ex2f(acc[mt][nt][2] * SCALE_L2E)
                                    + ex2f(acc[mt][nt][3] * SCALE_L2E);
                }
        } else {
            #pragma unroll
            for (int mt = 0; mt < 2; mt++)
                #pragma unroll
                for (int nt = 0; nt < 8; nt++)
                    #pragma unroll
                    for (int c = 0; c < 4; c++) {
                        int r  = wm * 32 + mt * 16 + ((c >> 1) & 1) * 8 + g;
                        int cc = wn * 64 + nt * 8 + t * 2 + (c & 1);
                        float e = ex2f(acc[mt][nt][c] * SCALE_L2E);
                        rs[mt * 2 + (c >> 1)] += (r == cc) ? 0.f : e;
                    }
        }
        __syncthreads();   // all reads of coff done before it is refilled
    }

    // reduce: quad (t lanes) -> shared (wn) -> global
    #pragma unroll
    for (int r = 0; r < 4; r++) {
        rs[r] += __shfl_xor_sync(0xFFFFFFFFu, rs[r], 1);
        rs[r] += __shfl_xor_sync(0xFFFFFFFFu, rs[r], 2);
    }
    float* srow = reinterpret_cast<float*>(smem);   // reuse, [2][BM]
    __syncthreads();
    if (t == 0) {
        #pragma unroll
        for (int r = 0; r < 4; r++) {
            int row_local = wm * 32 + (r >> 1) * 16 + (r & 1) * 8 + g;
            srow[wn * BM + row_local] = rs[r];
        }
    }
    __syncthreads();
    if (tid < BM)
        g_partial[(size_t)bz * N_ROWS + by * BM + tid] = srow[tid] + srow[BM + tid];
}

// ---------------------------------------------------------------------------
// Kernel 4a/4b: parallel deterministic reduction (self term already excluded).
__global__ void kred1() {
    __shared__ double red[256];
    const int tid = threadIdx.x;
    const int i = blockIdx.x * 256 + tid;
    float sv = 0.f;
    #pragma unroll
    for (int s = 0; s < SPLITS; s++) sv += g_partial[s * N_ROWS + i];
    red[tid] = (double)logf(sv) - (double)g_diag[i] * (double)INV_T;
    __syncthreads();
    #pragma unroll
    for (int o = 128; o > 0; o >>= 1) {
        if (tid < o) red[tid] += red[tid + o];
        __syncthreads();
    }
    if (tid == 0) g_red[blockIdx.x] = red[0];
}

__global__ void kred2(float* __restrict__ out) {
    __shared__ double red[64];
    const int tid = threadIdx.x;
    red[tid] = g_red[tid];
    __syncthreads();
    #pragma unroll
    for (int o = 32; o > 0; o >>= 1) {
        if (tid < o) red[tid] += red[tid + o];
        __syncthreads();
    }
    if (tid == 0) out[0] = (float)(red[0] / (double)N_ROWS);
}

// ---------------------------------------------------------------------------
extern "C" void kernel_launch(void* const* d_in, const int* in_sizes, int n_in,
                              void* d_out, int out_size) {
    const float* q = (const float*)d_in[0];
    const float* d = (const float*)d_in[1];

    cudaFuncSetAttribute(kmain, cudaFuncAttributeMaxDynamicSharedMemorySize,
                         SMEM_BYTES);

    knorm<<<(2 * N_ROWS) / 8, 256>>>(q, d);
    kdiag<<<N_ROWS / 8, 256>>>();
    kmain<<<dim3(N_ROWS / BM, SPLITS), 256, SMEM_BYTES>>>();
    kred1<<<64, 256>>>();
    kred2<<<1, 64>>>((float*)d_out);
}